// round 4
// baseline (speedup 1.0000x reference)
#include <cuda_runtime.h>

#define NT     256
#define NBINS  10
#define MAXCTA 4096

// Per-CTA partials: [cta][0..9]=cumulative loss sums (log2 units), [cta][10..19]=cumulative counts
__device__ float g_part[MAXCTA][2 * NBINS];

// T_k = -log2(1 - (k+1)/20): l < T_k  <=>  g < (k+1)/10   (cumulative bin membership)
#define T0 0.074000581443776925f
#define T1 0.152003093445049970f
#define T2 0.234465253637022970f
#define T3 0.321928094887362350f
#define T4 0.415037499278843800f
#define T5 0.514573172829758300f
#define T6 0.621488376746270400f
#define T7 0.736965594166206200f
#define T8 0.862501460807771400f
#define T9 1.0f

// l = log2(1 + e^d), d = x_other - x_target. Valid (g<1) <=> l < 1.
__device__ __forceinline__ float lossl(float dd, unsigned t) {
    float d = __int_as_float(__float_as_int(dd) ^ (int)(t << 31));
    float u; asm("ex2.approx.f32 %0, %1;" : "=f"(u) : "f"(d * 1.4426950408889634f));
    float v = 1.0f + u;
    float l; asm("lg2.approx.f32 %0, %1;" : "=f"(l) : "f"(v));
    return l;
}

#define BINADD(K, TK)                                                          \
    asm volatile("{\n\t.reg .pred p;\n\t"                                      \
                 "setp.lt.f32 p, %1, %2;\n\t"                                  \
                 "@p add.rn.f32x2 %0, %0, %3;\n\t}"                            \
                 : "+l"(acc[K]) : "f"(l), "f"(TK), "l"(lv));

__device__ __forceinline__ void process(float dd, unsigned t, unsigned long long* acc) {
    float l = lossl(dd, t);
    unsigned long long lv;  // packed (l, 1.0f): lane0 = loss, lane1 = count
    asm("mov.b64 %0, {%1, %2};" : "=l"(lv) : "f"(l), "f"(1.0f));
    BINADD(0, T0) BINADD(1, T1) BINADD(2, T2) BINADD(3, T3) BINADD(4, T4)
    BINADD(5, T5) BINADD(6, T6) BINADD(7, T7) BINADD(8, T8) BINADD(9, T9)
}

// One "quad" = 4 samples: two float4 of outputs + one uint4 of int32 targets.
__global__ void __launch_bounds__(NT)
ghm_main(const float4* __restrict__ o4, const uint4* __restrict__ t4,
         int nquads, int n) {
    __shared__ float s_red[2 * NBINS];
    const int tid = threadIdx.x;
    if (tid < 2 * NBINS) s_red[tid] = 0.0f;
    __syncthreads();

    unsigned long long acc[NBINS];
#pragma unroll
    for (int k = 0; k < NBINS; k++) acc[k] = 0ULL;

    const int stride = gridDim.x * blockDim.x;
    int i = blockIdx.x * blockDim.x + tid;

    // 2x unroll over quads: 6 independent 16B loads batched up front
    for (; i + stride < nquads; i += 2 * stride) {
        const int j = i + stride;
        float4 p0 = __ldcs(o4 + 2 * i);
        float4 q0 = __ldcs(o4 + 2 * i + 1);
        float4 p1 = __ldcs(o4 + 2 * j);
        float4 q1 = __ldcs(o4 + 2 * j + 1);
        uint4  t0 = __ldcs(t4 + i);
        uint4  t1 = __ldcs(t4 + j);
        process(p0.y - p0.x, t0.x, acc); process(p0.w - p0.z, t0.y, acc);
        process(q0.y - q0.x, t0.z, acc); process(q0.w - q0.z, t0.w, acc);
        process(p1.y - p1.x, t1.x, acc); process(p1.w - p1.z, t1.y, acc);
        process(q1.y - q1.x, t1.z, acc); process(q1.w - q1.z, t1.w, acc);
    }
    for (; i < nquads; i += stride) {
        float4 p = __ldcs(o4 + 2 * i);
        float4 q = __ldcs(o4 + 2 * i + 1);
        uint4  t = __ldcs(t4 + i);
        process(p.y - p.x, t.x, acc); process(p.w - p.z, t.y, acc);
        process(q.y - q.x, t.z, acc); process(q.w - q.z, t.w, acc);
    }
    // scalar tail (n % 4 != 0) — empty for N = 2^24
    for (int s = nquads * 4 + blockIdx.x * blockDim.x + tid; s < n; s += stride) {
        const float* o = (const float*)o4;
        const unsigned* tg = (const unsigned*)t4;
        process(o[2 * s + 1] - o[2 * s], tg[s], acc);
    }

    // unpack packed accumulators, warp -> block reduce, write per-CTA partials
#pragma unroll
    for (int k = 0; k < NBINS; k++) {
        float s = __uint_as_float((unsigned)(acc[k] & 0xffffffffULL));
        float c = __uint_as_float((unsigned)(acc[k] >> 32));
#pragma unroll
        for (int off = 16; off > 0; off >>= 1) {
            s += __shfl_xor_sync(0xffffffffu, s, off);
            c += __shfl_xor_sync(0xffffffffu, c, off);
        }
        if ((tid & 31) == 0) {
            atomicAdd(&s_red[k],         s);
            atomicAdd(&s_red[NBINS + k], c);
        }
    }
    __syncthreads();
    if (tid < 2 * NBINS) g_part[blockIdx.x][tid] = s_red[tid];
}

// 20 warps: warp w reduces column w of g_part; thread 0 finishes.
__global__ void ghm_finalize(const float* __restrict__ acc_sum,
                             float* __restrict__ out, int ncta) {
    __shared__ float red[2 * NBINS];
    const int w = threadIdx.x >> 5, lane = threadIdx.x & 31;
    if (w < 2 * NBINS) {
        float v = 0.0f;
        for (int i = lane; i < ncta; i += 32) v += g_part[i][w];
#pragma unroll
        for (int off = 16; off > 0; off >>= 1) v += __shfl_xor_sync(0xffffffffu, v, off);
        if (lane == 0) red[w] = v;
    }
    __syncthreads();
    if (threadIdx.x == 0) {
        float res = 0.0f, ps = 0.0f, pc = 0.0f;
#pragma unroll
        for (int b = 0; b < NBINS; b++) {
            float cs = red[b], cc = red[NBINS + b];
            float sb = cs - ps, cb = cc - pc;   // per-bin (sum, count) from cumulative
            ps = cs; pc = cc;
            if (cb > 0.0f) {
                float na = 0.75f * acc_sum[b] + 0.25f * cb;
                res += sb * 0.6931471805599453f / na;  // ln2: sums are in log2 units
            }
        }
        out[0] = res;
    }
}

extern "C" void kernel_launch(void* const* d_in, const int* in_sizes, int n_in,
                              void* d_out, int out_size) {
    // Identify inputs BY SIZE: outputs = largest (2N f32); acc_sum = 10 f32; targets = rest (N i32)
    int i_out = 0;
    for (int i = 1; i < n_in; i++) if (in_sizes[i] > in_sizes[i_out]) i_out = i;
    int i_acc = -1;
    for (int i = 0; i < n_in; i++) if (i != i_out && in_sizes[i] == NBINS) { i_acc = i; break; }
    if (i_acc < 0) {
        for (int i = 0; i < n_in; i++)
            if (i != i_out && (i_acc < 0 || in_sizes[i] < in_sizes[i_acc])) i_acc = i;
    }
    int i_tgt = 0;
    for (int i = 0; i < n_in; i++) if (i != i_out && i != i_acc) { i_tgt = i; break; }

    const float4* o4  = (const float4*)d_in[i_out];
    const uint4*  t4  = (const uint4*)d_in[i_tgt];
    const float*  acc = (const float*)d_in[i_acc];
    const int n = in_sizes[i_tgt];
    const int nquads = n / 4;

    int sms = 148;
    cudaDeviceGetAttribute(&sms, cudaDevAttrMultiProcessorCount, 0);
    int ncta = sms * 12;
    if (ncta > MAXCTA) ncta = MAXCTA;

    ghm_main<<<ncta, NT>>>(o4, t4, nquads, n);
    ghm_finalize<<<1, 32 * 2 * NBINS>>>(acc, (float*)d_out, ncta);
}

// round 5
// speedup vs baseline: 1.0270x; 1.0270x over previous
#include <cuda_runtime.h>

#define NT     256
#define NBINS  10

__device__ float    g_sum[NBINS];   // cumulative loss sums (log2 units)
__device__ float    g_cnt[NBINS];   // cumulative counts
__device__ unsigned g_done;         // CTA completion ticket

// T_k = -log2(1 - (k+1)/20): l < T_k  <=>  g < (k+1)/10   (cumulative bins)
#define T0 0.074000581443776925f
#define T1 0.152003093445049970f
#define T2 0.234465253637022970f
#define T3 0.321928094887362350f
#define T4 0.415037499278843800f
#define T5 0.514573172829758300f
#define T6 0.621488376746270400f
#define T7 0.736965594166206200f
#define T8 0.862501460807771400f
#define T9 1.0f

// l = log2(1 + e^d), d = x_other - x_target. Valid (g<1) <=> l < 1.
__device__ __forceinline__ float lossl(float dd, unsigned t) {
    float d = __int_as_float(__float_as_int(dd) ^ (int)(t << 31));
    float u; asm("ex2.approx.f32 %0, %1;" : "=f"(u) : "f"(d * 1.4426950408889634f));
    float v = 1.0f + u;
    float l; asm("lg2.approx.f32 %0, %1;" : "=f"(l) : "f"(v));
    return l;
}

#define BINADD(K, TK)                                                          \
    asm volatile("{\n\t.reg .pred p;\n\t"                                      \
                 "setp.lt.f32 p, %1, %2;\n\t"                                  \
                 "@p add.rn.f32x2 %0, %0, %3;\n\t}"                            \
                 : "+l"(acc[K]) : "f"(l), "f"(TK), "l"(lv));

__device__ __forceinline__ void process(float dd, unsigned t, unsigned long long* acc) {
    float l = lossl(dd, t);
    unsigned long long lv;  // packed (l, 1.0f): lane0 = loss, lane1 = count
    asm("mov.b64 %0, {%1, %2};" : "=l"(lv) : "f"(l), "f"(1.0f));
    BINADD(0, T0) BINADD(1, T1) BINADD(2, T2) BINADD(3, T3) BINADD(4, T4)
    BINADD(5, T5) BINADD(6, T6) BINADD(7, T7) BINADD(8, T8) BINADD(9, T9)
}

// Single fused kernel: stream + bin + block-reduce + global atomics;
// last CTA finalizes, writes out, and resets globals for the next graph replay.
__global__ void __launch_bounds__(NT)
ghm_main(const float4* __restrict__ o4, const uint4* __restrict__ t4,
         int nquads, int n, const float* __restrict__ acc_sum,
         float* __restrict__ out, int ncta) {
    __shared__ float s_red[2 * NBINS];
    __shared__ unsigned s_last;
    const int tid = threadIdx.x;
    if (tid < 2 * NBINS) s_red[tid] = 0.0f;
    __syncthreads();

    unsigned long long acc[NBINS];
#pragma unroll
    for (int k = 0; k < NBINS; k++) acc[k] = 0ULL;

    const int stride = gridDim.x * blockDim.x;
    int i = blockIdx.x * blockDim.x + tid;

    // 2x unroll over quads (quad = 4 samples): 6 independent 16B loads up front
    for (; i + stride < nquads; i += 2 * stride) {
        const int j = i + stride;
        float4 p0 = __ldcs(o4 + 2 * i);
        float4 q0 = __ldcs(o4 + 2 * i + 1);
        float4 p1 = __ldcs(o4 + 2 * j);
        float4 q1 = __ldcs(o4 + 2 * j + 1);
        uint4  t0 = __ldcs(t4 + i);
        uint4  t1 = __ldcs(t4 + j);
        process(p0.y - p0.x, t0.x, acc); process(p0.w - p0.z, t0.y, acc);
        process(q0.y - q0.x, t0.z, acc); process(q0.w - q0.z, t0.w, acc);
        process(p1.y - p1.x, t1.x, acc); process(p1.w - p1.z, t1.y, acc);
        process(q1.y - q1.x, t1.z, acc); process(q1.w - q1.z, t1.w, acc);
    }
    for (; i < nquads; i += stride) {
        float4 p = __ldcs(o4 + 2 * i);
        float4 q = __ldcs(o4 + 2 * i + 1);
        uint4  t = __ldcs(t4 + i);
        process(p.y - p.x, t.x, acc); process(p.w - p.z, t.y, acc);
        process(q.y - q.x, t.z, acc); process(q.w - q.z, t.w, acc);
    }
    // scalar tail (n % 4 != 0) — empty for N = 2^24
    for (int s = nquads * 4 + blockIdx.x * blockDim.x + tid; s < n; s += stride) {
        const float* o = (const float*)o4;
        const unsigned* tg = (const unsigned*)t4;
        process(o[2 * s + 1] - o[2 * s], tg[s], acc);
    }

    // unpack, warp -> block reduce
#pragma unroll
    for (int k = 0; k < NBINS; k++) {
        float s = __uint_as_float((unsigned)(acc[k] & 0xffffffffULL));
        float c = __uint_as_float((unsigned)(acc[k] >> 32));
#pragma unroll
        for (int off = 16; off > 0; off >>= 1) {
            s += __shfl_xor_sync(0xffffffffu, s, off);
            c += __shfl_xor_sync(0xffffffffu, c, off);
        }
        if ((tid & 31) == 0) {
            atomicAdd(&s_red[k],         s);
            atomicAdd(&s_red[NBINS + k], c);
        }
    }
    __syncthreads();

    // CTA partial -> global atomics (20 addresses, L2-atomic cheap)
    if (tid < NBINS)           atomicAdd(&g_sum[tid],         s_red[tid]);
    else if (tid < 2 * NBINS)  atomicAdd(&g_cnt[tid - NBINS], s_red[tid]);
    __threadfence();
    if (tid == 0) s_last = (atomicAdd(&g_done, 1u) == (unsigned)(ncta - 1));
    __syncthreads();

    // Last CTA: finalize, write output, reset state for the next graph replay
    if (s_last && tid == 0) {
        float res = 0.0f, ps = 0.0f, pc = 0.0f;
#pragma unroll
        for (int b = 0; b < NBINS; b++) {
            float cs = atomicAdd(&g_sum[b], 0.0f);   // coherent L2 read
            float cc = atomicAdd(&g_cnt[b], 0.0f);
            float sb = cs - ps, cb = cc - pc;        // per-bin from cumulative
            ps = cs; pc = cc;
            if (cb > 0.0f) {
                float na = 0.75f * acc_sum[b] + 0.25f * cb;
                res += sb * 0.6931471805599453f / na;  // ln2: sums in log2 units
            }
        }
        out[0] = res;
#pragma unroll
        for (int b = 0; b < NBINS; b++) { g_sum[b] = 0.0f; g_cnt[b] = 0.0f; }
        g_done = 0u;
    }
}

extern "C" void kernel_launch(void* const* d_in, const int* in_sizes, int n_in,
                              void* d_out, int out_size) {
    // Identify inputs BY SIZE: outputs = largest (2N f32); acc_sum = 10 f32; targets = rest (N i32)
    int i_out = 0;
    for (int i = 1; i < n_in; i++) if (in_sizes[i] > in_sizes[i_out]) i_out = i;
    int i_acc = -1;
    for (int i = 0; i < n_in; i++) if (i != i_out && in_sizes[i] == NBINS) { i_acc = i; break; }
    if (i_acc < 0) {
        for (int i = 0; i < n_in; i++)
            if (i != i_out && (i_acc < 0 || in_sizes[i] < in_sizes[i_acc])) i_acc = i;
    }
    int i_tgt = 0;
    for (int i = 0; i < n_in; i++) if (i != i_out && i != i_acc) { i_tgt = i; break; }

    const float4* o4  = (const float4*)d_in[i_out];
    const uint4*  t4  = (const uint4*)d_in[i_tgt];
    const float*  acc = (const float*)d_in[i_acc];
    const int n = in_sizes[i_tgt];
    const int nquads = n / 4;

    int sms = 148;
    cudaDeviceGetAttribute(&sms, cudaDevAttrMultiProcessorCount, 0);
    const int ncta = sms * 12;

    ghm_main<<<ncta, NT>>>(o4, t4, nquads, n, acc, (float*)d_out, ncta);
}

// round 6
// speedup vs baseline: 1.0644x; 1.0365x over previous
#include <cuda_runtime.h>

#define NT     256
#define NBINS  10

__device__ float    g_sum[NBINS];
__device__ float    g_cnt[NBINS];
__device__ unsigned g_done;

// Per-sample: d = x_other - x_target
//   v = 1 + e^d ; l = log2(v) = loss in log2 units ; r = 1/v = p_target
//   g = 2(1-r); bin = floor(10g) = floor(20 - 20r); valid <=> bin < 10
// One predicated smem f32x2 accumulate: hist[bin][tid] += (l, 1)
__device__ __forceinline__ void process(float dd, unsigned t, unsigned hbase) {
    float d = __int_as_float(__float_as_int(dd) ^ (int)(t << 31));
    float u; asm("ex2.approx.f32 %0, %1;" : "=f"(u) : "f"(d * 1.4426950408889634f));
    float v = 1.0f + u;
    float l; asm("lg2.approx.f32 %0, %1;" : "=f"(l) : "f"(v));
    float r; asm("rcp.approx.f32 %0, %1;" : "=f"(r) : "f"(v));
    float s = fmaf(-20.0f, r, 20.0f);
    int b = (int)s;                       // trunc; in [0,20]
    unsigned long long lv;
    asm("mov.b64 %0, {%1, %2};" : "=l"(lv) : "f"(l), "f"(1.0f));
    unsigned addr = hbase + ((unsigned)b << 11);   // [bin][tid], 2048B per bin
    asm volatile("{\n\t.reg .pred p;\n\t.reg .b64 hv;\n\t"
                 "setp.lt.s32 p, %0, 10;\n\t"
                 "@p ld.shared.b64 hv, [%1];\n\t"
                 "@p add.rn.f32x2 hv, hv, %2;\n\t"
                 "@p st.shared.b64 [%1], hv;\n\t}"
                 :: "r"(b), "r"(addr), "l"(lv) : "memory");
}

__global__ void __launch_bounds__(NT)
ghm_main(const float4* __restrict__ o4, const uint4* __restrict__ t4,
         int nquads, int n, const float* __restrict__ acc_sum,
         float* __restrict__ out, int ncta) {
    __shared__ float2 hist[NBINS][NT];    // [bin][tid] -> conflict-free LDS.64
    __shared__ float s_red[2 * NBINS];
    __shared__ unsigned s_last;

    const int tid = threadIdx.x;
    if (tid < 2 * NBINS) s_red[tid] = 0.0f;
#pragma unroll
    for (int k = 0; k < NBINS; k++) hist[k][tid] = make_float2(0.0f, 0.0f);
    __syncthreads();

    unsigned hbase;
    asm("{ .reg .u64 a; cvta.to.shared.u64 a, %1; cvt.u32.u64 %0, a; }"
        : "=r"(hbase) : "l"((void*)&hist[0][tid]));

    const int stride = gridDim.x * blockDim.x;
    int i = blockIdx.x * blockDim.x + tid;

    // 2x unroll over quads (quad = 4 samples): 6 independent 16B loads up front
    for (; i + stride < nquads; i += 2 * stride) {
        const int j = i + stride;
        float4 p0 = __ldcs(o4 + 2 * i);
        float4 q0 = __ldcs(o4 + 2 * i + 1);
        float4 p1 = __ldcs(o4 + 2 * j);
        float4 q1 = __ldcs(o4 + 2 * j + 1);
        uint4  t0 = __ldcs(t4 + i);
        uint4  t1 = __ldcs(t4 + j);
        process(p0.y - p0.x, t0.x, hbase); process(p0.w - p0.z, t0.y, hbase);
        process(q0.y - q0.x, t0.z, hbase); process(q0.w - q0.z, t0.w, hbase);
        process(p1.y - p1.x, t1.x, hbase); process(p1.w - p1.z, t1.y, hbase);
        process(q1.y - q1.x, t1.z, hbase); process(q1.w - q1.z, t1.w, hbase);
    }
    for (; i < nquads; i += stride) {
        float4 p = __ldcs(o4 + 2 * i);
        float4 q = __ldcs(o4 + 2 * i + 1);
        uint4  t = __ldcs(t4 + i);
        process(p.y - p.x, t.x, hbase); process(p.w - p.z, t.y, hbase);
        process(q.y - q.x, t.z, hbase); process(q.w - q.z, t.w, hbase);
    }
    // scalar tail (n % 4 != 0) — empty for N = 2^24
    for (int s = nquads * 4 + blockIdx.x * blockDim.x + tid; s < n; s += stride) {
        const float* o = (const float*)o4;
        const unsigned* tg = (const unsigned*)t4;
        process(o[2 * s + 1] - o[2 * s], tg[s], hbase);
    }
    __syncthreads();

    // hist -> warp reduce -> block partials
#pragma unroll
    for (int k = 0; k < NBINS; k++) {
        float2 hv = hist[k][tid];
        float s = hv.x, c = hv.y;
#pragma unroll
        for (int off = 16; off > 0; off >>= 1) {
            s += __shfl_xor_sync(0xffffffffu, s, off);
            c += __shfl_xor_sync(0xffffffffu, c, off);
        }
        if ((tid & 31) == 0) {
            atomicAdd(&s_red[k],         s);
            atomicAdd(&s_red[NBINS + k], c);
        }
    }
    __syncthreads();

    // CTA partials -> global atomics (20 addresses)
    if (tid < NBINS)           atomicAdd(&g_sum[tid],         s_red[tid]);
    else if (tid < 2 * NBINS)  atomicAdd(&g_cnt[tid - NBINS], s_red[tid]);
    __threadfence();
    if (tid == 0) s_last = (atomicAdd(&g_done, 1u) == (unsigned)(ncta - 1));
    __syncthreads();

    // Last CTA: finalize (direct bins), write out, reset for next graph replay
    if (s_last && tid == 0) {
        float res = 0.0f;
#pragma unroll
        for (int b = 0; b < NBINS; b++) {
            float sb = atomicAdd(&g_sum[b], 0.0f);
            float cb = atomicAdd(&g_cnt[b], 0.0f);
            if (cb > 0.0f) {
                float na = 0.75f * acc_sum[b] + 0.25f * cb;
                res += sb * 0.6931471805599453f / na;  // ln2: sums in log2 units
            }
        }
        out[0] = res;
#pragma unroll
        for (int b = 0; b < NBINS; b++) { g_sum[b] = 0.0f; g_cnt[b] = 0.0f; }
        g_done = 0u;
    }
}

extern "C" void kernel_launch(void* const* d_in, const int* in_sizes, int n_in,
                              void* d_out, int out_size) {
    // Identify inputs BY SIZE: outputs = largest (2N f32); acc_sum = 10 f32; targets = rest (N i32)
    int i_out = 0;
    for (int i = 1; i < n_in; i++) if (in_sizes[i] > in_sizes[i_out]) i_out = i;
    int i_acc = -1;
    for (int i = 0; i < n_in; i++) if (i != i_out && in_sizes[i] == NBINS) { i_acc = i; break; }
    if (i_acc < 0) {
        for (int i = 0; i < n_in; i++)
            if (i != i_out && (i_acc < 0 || in_sizes[i] < in_sizes[i_acc])) i_acc = i;
    }
    int i_tgt = 0;
    for (int i = 0; i < n_in; i++) if (i != i_out && i != i_acc) { i_tgt = i; break; }

    const float4* o4  = (const float4*)d_in[i_out];
    const uint4*  t4  = (const uint4*)d_in[i_tgt];
    const float*  acc = (const float*)d_in[i_acc];
    const int n = in_sizes[i_tgt];
    const int nquads = n / 4;

    int sms = 148;
    cudaDeviceGetAttribute(&sms, cudaDevAttrMultiProcessorCount, 0);
    const int ncta = sms * 8;   // one full resident wave at 8 CTAs/SM

    ghm_main<<<ncta, NT>>>(o4, t4, nquads, n, acc, (float*)d_out, ncta);
}

// round 7
// speedup vs baseline: 1.1604x; 1.0901x over previous
#include <cuda_runtime.h>

#define NT     256
#define NBINS  10

__device__ float    g_sum[NBINS];
__device__ float    g_cnt[NBINS];
__device__ unsigned g_done;

// Per-sample: d = x_other - x_target
//   v = 1 + e^d ; l = log2(v) ; r = 1/v = p_target
//   bin = floor(20 - 20r); valid <=> bin < 10
// One predicated smem f32x2 accumulate: hist[bin][tid] += (l, 1)
__device__ __forceinline__ void process(float dd, unsigned t, unsigned hbase) {
    float d = __int_as_float(__float_as_int(dd) ^ (int)(t << 31));
    float u; asm("ex2.approx.f32 %0, %1;" : "=f"(u) : "f"(d * 1.4426950408889634f));
    float v = 1.0f + u;
    float l; asm("lg2.approx.f32 %0, %1;" : "=f"(l) : "f"(v));
    float r; asm("rcp.approx.f32 %0, %1;" : "=f"(r) : "f"(v));
    float s = fmaf(-20.0f, r, 20.0f);
    int b = (int)s;                       // trunc; in [0,20]
    unsigned long long lv;
    asm("mov.b64 %0, {%1, %2};" : "=l"(lv) : "f"(l), "f"(1.0f));
    unsigned addr = hbase + ((unsigned)b << 11);   // [bin][tid], 2048B bin stride
    asm volatile("{\n\t.reg .pred p;\n\t.reg .b64 hv;\n\t"
                 "setp.lt.s32 p, %0, 10;\n\t"
                 "@p ld.shared.b64 hv, [%1];\n\t"
                 "@p add.rn.f32x2 hv, hv, %2;\n\t"
                 "@p st.shared.b64 [%1], hv;\n\t}"
                 :: "r"(b), "r"(addr), "l"(lv) : "memory");
}

__global__ void __launch_bounds__(NT)
ghm_main(const float4* __restrict__ o4, const uint4* __restrict__ t4,
         int nquads, int n, const float* __restrict__ acc_sum,
         float* __restrict__ out, int ncta) {
    __shared__ float2 hist[NBINS][NT];    // [bin][tid] -> conflict-free LDS.64
    __shared__ float s_red[2 * NBINS];
    __shared__ unsigned s_last;

    const int tid = threadIdx.x;
    if (tid < 2 * NBINS) s_red[tid] = 0.0f;
#pragma unroll
    for (int k = 0; k < NBINS; k++) hist[k][tid] = make_float2(0.0f, 0.0f);
    __syncthreads();

    unsigned hbase;
    asm("{ .reg .u64 a; cvta.to.shared.u64 a, %1; cvt.u32.u64 %0, a; }"
        : "=r"(hbase) : "l"((void*)&hist[0][tid]));

    const int stride = gridDim.x * blockDim.x;
    int i = blockIdx.x * blockDim.x + tid;

    // 4x unroll over quads (quad = 4 samples): 12 independent 16B loads up front (MLP=12)
    for (; i + 3 * stride < nquads; i += 4 * stride) {
        const int i0 = i, i1 = i + stride, i2 = i + 2 * stride, i3 = i + 3 * stride;
        float4 p0 = __ldcs(o4 + 2 * i0),     p1 = __ldcs(o4 + 2 * i1);
        float4 p2 = __ldcs(o4 + 2 * i2),     p3 = __ldcs(o4 + 2 * i3);
        float4 q0 = __ldcs(o4 + 2 * i0 + 1), q1 = __ldcs(o4 + 2 * i1 + 1);
        float4 q2 = __ldcs(o4 + 2 * i2 + 1), q3 = __ldcs(o4 + 2 * i3 + 1);
        uint4  t0 = __ldcs(t4 + i0), t1 = __ldcs(t4 + i1);
        uint4  t2 = __ldcs(t4 + i2), t3 = __ldcs(t4 + i3);

        process(p0.y - p0.x, t0.x, hbase); process(p0.w - p0.z, t0.y, hbase);
        process(q0.y - q0.x, t0.z, hbase); process(q0.w - q0.z, t0.w, hbase);
        process(p1.y - p1.x, t1.x, hbase); process(p1.w - p1.z, t1.y, hbase);
        process(q1.y - q1.x, t1.z, hbase); process(q1.w - q1.z, t1.w, hbase);
        process(p2.y - p2.x, t2.x, hbase); process(p2.w - p2.z, t2.y, hbase);
        process(q2.y - q2.x, t2.z, hbase); process(q2.w - q2.z, t2.w, hbase);
        process(p3.y - p3.x, t3.x, hbase); process(p3.w - p3.z, t3.y, hbase);
        process(q3.y - q3.x, t3.z, hbase); process(q3.w - q3.z, t3.w, hbase);
    }
    for (; i < nquads; i += stride) {
        float4 p = __ldcs(o4 + 2 * i);
        float4 q = __ldcs(o4 + 2 * i + 1);
        uint4  t = __ldcs(t4 + i);
        process(p.y - p.x, t.x, hbase); process(p.w - p.z, t.y, hbase);
        process(q.y - q.x, t.z, hbase); process(q.w - q.z, t.w, hbase);
    }
    // scalar tail (n % 4 != 0) — empty for N = 2^24
    for (int s = nquads * 4 + blockIdx.x * blockDim.x + tid; s < n; s += stride) {
        const float* o = (const float*)o4;
        const unsigned* tg = (const unsigned*)t4;
        process(o[2 * s + 1] - o[2 * s], tg[s], hbase);
    }
    __syncthreads();

    // hist -> warp reduce -> block partials
#pragma unroll
    for (int k = 0; k < NBINS; k++) {
        float2 hv = hist[k][tid];
        float s = hv.x, c = hv.y;
#pragma unroll
        for (int off = 16; off > 0; off >>= 1) {
            s += __shfl_xor_sync(0xffffffffu, s, off);
            c += __shfl_xor_sync(0xffffffffu, c, off);
        }
        if ((tid & 31) == 0) {
            atomicAdd(&s_red[k],         s);
            atomicAdd(&s_red[NBINS + k], c);
        }
    }
    __syncthreads();

    // CTA partials -> global atomics (20 addresses)
    if (tid < NBINS)           atomicAdd(&g_sum[tid],         s_red[tid]);
    else if (tid < 2 * NBINS)  atomicAdd(&g_cnt[tid - NBINS], s_red[tid]);
    __threadfence();
    if (tid == 0) s_last = (atomicAdd(&g_done, 1u) == (unsigned)(ncta - 1));
    __syncthreads();

    // Last CTA: finalize, write output, reset state for next graph replay
    if (s_last && tid == 0) {
        float res = 0.0f;
#pragma unroll
        for (int b = 0; b < NBINS; b++) {
            float sb = atomicAdd(&g_sum[b], 0.0f);
            float cb = atomicAdd(&g_cnt[b], 0.0f);
            if (cb > 0.0f) {
                float na = 0.75f * acc_sum[b] + 0.25f * cb;
                res += sb * 0.6931471805599453f / na;  // ln2: sums in log2 units
            }
        }
        out[0] = res;
#pragma unroll
        for (int b = 0; b < NBINS; b++) { g_sum[b] = 0.0f; g_cnt[b] = 0.0f; }
        g_done = 0u;
    }
}

extern "C" void kernel_launch(void* const* d_in, const int* in_sizes, int n_in,
                              void* d_out, int out_size) {
    // Identify inputs BY SIZE: outputs = largest (2N f32); acc_sum = 10 f32; targets = rest (N i32)
    int i_out = 0;
    for (int i = 1; i < n_in; i++) if (in_sizes[i] > in_sizes[i_out]) i_out = i;
    int i_acc = -1;
    for (int i = 0; i < n_in; i++) if (i != i_out && in_sizes[i] == NBINS) { i_acc = i; break; }
    if (i_acc < 0) {
        for (int i = 0; i < n_in; i++)
            if (i != i_out && (i_acc < 0 || in_sizes[i] < in_sizes[i_acc])) i_acc = i;
    }
    int i_tgt = 0;
    for (int i = 0; i < n_in; i++) if (i != i_out && i != i_acc) { i_tgt = i; break; }

    const float4* o4  = (const float4*)d_in[i_out];
    const uint4*  t4  = (const uint4*)d_in[i_tgt];
    const float*  acc = (const float*)d_in[i_acc];
    const int n = in_sizes[i_tgt];
    const int nquads = n / 4;

    int sms = 148;
    cudaDeviceGetAttribute(&sms, cudaDevAttrMultiProcessorCount, 0);
    const int ncta = sms * 8;

    ghm_main<<<ncta, NT>>>(o4, t4, nquads, n, acc, (float*)d_out, ncta);
}